// round 1
// baseline (speedup 1.0000x reference)
#include <cuda_runtime.h>

#define BB 4
#define SS 2048
#define DD 512
#define HH 8
#define DKK 64
#define MTOK (BB*SS)   // 8192 token rows

// Scratch (module-load allocated; no cudaMalloc anywhere)
__device__ float g_q[MTOK*DD];
__device__ float g_k[MTOK*DD];
__device__ float g_v[MTOK*DD];
__device__ float g_ctx[MTOK*DD];
__device__ float g_y[MTOK*DD];

// ----------------------------------------------------------------------------
// GEMM: C[m][n] = sum_k A[m][k] * W[n][k] + bias[n] (+ res[m*N+n] if res!=null)
// BM=BN=64, BK=16, 256 threads, 4x4 per thread.
// ----------------------------------------------------------------------------
__global__ __launch_bounds__(256) void gemm_xwt_kernel(
    const float* __restrict__ A, const float* __restrict__ W,
    const float* __restrict__ bias, const float* __restrict__ res,
    float* __restrict__ C, int Mdim, int Ndim, int Kdim)
{
    __shared__ float As[16][68];   // [k][m]
    __shared__ float Bs[16][68];   // [k][n]
    const int tx = threadIdx.x & 15;
    const int ty = threadIdx.x >> 4;
    const int m0 = blockIdx.y * 64;
    const int n0 = blockIdx.x * 64;
    const int lr  = threadIdx.x >> 2;   // 0..63
    const int lc4 = threadIdx.x & 3;    // 0..3 (float4 index within BK=16)

    float acc[4][4];
#pragma unroll
    for (int i = 0; i < 4; i++)
#pragma unroll
        for (int j = 0; j < 4; j++) acc[i][j] = 0.f;

    for (int k0 = 0; k0 < Kdim; k0 += 16) {
        float4 av = *(const float4*)(A + (size_t)(m0 + lr) * Kdim + k0 + lc4 * 4);
        float4 bv = *(const float4*)(W + (size_t)(n0 + lr) * Kdim + k0 + lc4 * 4);
        __syncthreads();
        As[lc4*4+0][lr] = av.x; As[lc4*4+1][lr] = av.y;
        As[lc4*4+2][lr] = av.z; As[lc4*4+3][lr] = av.w;
        Bs[lc4*4+0][lr] = bv.x; Bs[lc4*4+1][lr] = bv.y;
        Bs[lc4*4+2][lr] = bv.z; Bs[lc4*4+3][lr] = bv.w;
        __syncthreads();
#pragma unroll
        for (int k = 0; k < 16; k++) {
            float4 a4 = *(const float4*)&As[k][ty*4];
            float4 b4 = *(const float4*)&Bs[k][tx*4];
            float ar[4] = {a4.x, a4.y, a4.z, a4.w};
            float br[4] = {b4.x, b4.y, b4.z, b4.w};
#pragma unroll
            for (int i = 0; i < 4; i++)
#pragma unroll
                for (int j = 0; j < 4; j++)
                    acc[i][j] += ar[i] * br[j];
        }
    }

#pragma unroll
    for (int i = 0; i < 4; i++) {
        const int m = m0 + ty*4 + i;
#pragma unroll
        for (int j = 0; j < 4; j++) {
            const int n = n0 + tx*4 + j;
            float v = acc[i][j] + bias[n];
            if (res) v += res[(size_t)m * Ndim + n];
            C[(size_t)m * Ndim + n] = v;
        }
    }
}

// ----------------------------------------------------------------------------
// Flash attention: per (b,h), BM=64 query rows per block, stream keys BN=32.
// 256 threads: tx=0..15 (2 score cols / 4 out cols), ty=0..15 (4 rows).
// qs/ks stored transposed [d][row] so inner loops use vector LDS.
// ----------------------------------------------------------------------------
__global__ __launch_bounds__(256) void attn_kernel()
{
    __shared__ float qs[64][68];   // [d][qrow], pre-scaled by 1/sqrt(dk)
    __shared__ float ks[64][36];   // [d][kcol]
    __shared__ float vs[32][68];   // [kt][d]
    __shared__ float ps[32][68];   // [kt][qrow]

    const int bh = blockIdx.y;
    const size_t base = (size_t)(bh / HH) * SS * DD + (size_t)(bh % HH) * DKK;
    const float* qp = g_q + base;
    const float* kp = g_k + base;
    const float* vp = g_v + base;
    float* op = g_ctx + base;

    const int q0 = blockIdx.x * 64;
    const int tid = threadIdx.x;
    const int tx = tid & 15;
    const int ty = tid >> 4;

    for (int i = tid; i < 64 * 64; i += 256) {
        int r = i >> 6, d = i & 63;
        qs[d][r] = qp[(size_t)(q0 + r) * DD + d] * 0.125f;  // 1/sqrt(64)
    }

    float mrow[4], lrow[4], acc[4][4];
#pragma unroll
    for (int i = 0; i < 4; i++) {
        mrow[i] = -1e30f; lrow[i] = 0.f;
#pragma unroll
        for (int j = 0; j < 4; j++) acc[i][j] = 0.f;
    }

    for (int k0 = 0; k0 < SS; k0 += 32) {
        __syncthreads();   // prior iter's ks/vs/ps reads done
        for (int i = tid; i < 32 * 64; i += 256) {
            int r = i >> 6, d = i & 63;
            ks[d][r] = kp[(size_t)(k0 + r) * DD + d];
            vs[r][d] = vp[(size_t)(k0 + r) * DD + d];
        }
        __syncthreads();

        // scores: s[r][c] = q_row . k_col (q pre-scaled)
        float s[4][2] = {{0.f,0.f},{0.f,0.f},{0.f,0.f},{0.f,0.f}};
#pragma unroll
        for (int d = 0; d < 64; d++) {
            float4 q4 = *(const float4*)&qs[d][ty*4];
            float2 k2 = *(const float2*)&ks[d][tx*2];
            s[0][0] += q4.x*k2.x; s[0][1] += q4.x*k2.y;
            s[1][0] += q4.y*k2.x; s[1][1] += q4.y*k2.y;
            s[2][0] += q4.z*k2.x; s[2][1] += q4.z*k2.y;
            s[3][0] += q4.w*k2.x; s[3][1] += q4.w*k2.y;
        }

        // online softmax (row reductions across 16 tx lanes of each half-warp)
#pragma unroll
        for (int r = 0; r < 4; r++) {
            float mx = fmaxf(s[r][0], s[r][1]);
#pragma unroll
            for (int o = 1; o < 16; o <<= 1)
                mx = fmaxf(mx, __shfl_xor_sync(0xffffffffu, mx, o));
            float mn = fmaxf(mrow[r], mx);
            float p0 = __expf(s[r][0] - mn);
            float p1 = __expf(s[r][1] - mn);
            float rs = p0 + p1;
#pragma unroll
            for (int o = 1; o < 16; o <<= 1)
                rs += __shfl_xor_sync(0xffffffffu, rs, o);
            float sc = __expf(mrow[r] - mn);
            lrow[r] = lrow[r] * sc + rs;
            mrow[r] = mn;
#pragma unroll
            for (int j = 0; j < 4; j++) acc[r][j] *= sc;
            s[r][0] = p0; s[r][1] = p1;
        }

        // share P through smem: ps[kt][qrow]
#pragma unroll
        for (int r = 0; r < 4; r++) {
            ps[tx*2 + 0][ty*4 + r] = s[r][0];
            ps[tx*2 + 1][ty*4 + r] = s[r][1];
        }
        __syncthreads();

        // acc += P @ V
#pragma unroll
        for (int kt = 0; kt < 32; kt++) {
            float4 p4 = *(const float4*)&ps[kt][ty*4];
            float4 v4 = *(const float4*)&vs[kt][tx*4];
            float pr[4] = {p4.x, p4.y, p4.z, p4.w};
            float vr[4] = {v4.x, v4.y, v4.z, v4.w};
#pragma unroll
            for (int i = 0; i < 4; i++)
#pragma unroll
                for (int j = 0; j < 4; j++)
                    acc[i][j] += pr[i] * vr[j];
        }
    }

#pragma unroll
    for (int r = 0; r < 4; r++) {
        float inv = 1.f / lrow[r];
#pragma unroll
        for (int j = 0; j < 4; j++)
            op[(size_t)(q0 + ty*4 + r) * DD + tx*4 + j] = acc[r][j] * inv;
    }
}

// ----------------------------------------------------------------------------
// LayerNorm: one block (128 thr) per token row of 512
// ----------------------------------------------------------------------------
__global__ __launch_bounds__(128) void ln_kernel(
    const float* __restrict__ y, const float* __restrict__ gamma,
    const float* __restrict__ beta, float* __restrict__ out)
{
    const int row = blockIdx.x;
    const float* yr = y + (size_t)row * DD;
    float v[4], s = 0.f, s2 = 0.f;
#pragma unroll
    for (int i = 0; i < 4; i++) {
        float t = yr[threadIdx.x + i * 128];
        v[i] = t; s += t; s2 += t * t;
    }
#pragma unroll
    for (int o = 16; o; o >>= 1) {
        s  += __shfl_xor_sync(0xffffffffu, s, o);
        s2 += __shfl_xor_sync(0xffffffffu, s2, o);
    }
    __shared__ float sh[8];
    const int w = threadIdx.x >> 5;
    if ((threadIdx.x & 31) == 0) { sh[w] = s; sh[w + 4] = s2; }
    __syncthreads();
    s  = sh[0] + sh[1] + sh[2] + sh[3];
    s2 = sh[4] + sh[5] + sh[6] + sh[7];
    const float mu   = s * (1.f / DD);
    const float var  = s2 * (1.f / DD) - mu * mu;
    const float rstd = rsqrtf(var + 1e-5f);
    float* orow = out + (size_t)row * DD;
#pragma unroll
    for (int i = 0; i < 4; i++) {
        const int c = threadIdx.x + i * 128;
        orow[c] = (v[i] - mu) * rstd * gamma[c] + beta[c];
    }
}

// ----------------------------------------------------------------------------
extern "C" void kernel_launch(void* const* d_in, const int* in_sizes, int n_in,
                              void* d_out, int out_size)
{
    const float* x     = (const float*)d_in[0];
    const float* Wq    = (const float*)d_in[1];
    const float* bq    = (const float*)d_in[2];
    const float* Wk    = (const float*)d_in[3];
    const float* bk    = (const float*)d_in[4];
    const float* Wv    = (const float*)d_in[5];
    const float* bv    = (const float*)d_in[6];
    const float* Wo    = (const float*)d_in[7];
    const float* bo    = (const float*)d_in[8];
    const float* gamma = (const float*)d_in[9];
    const float* beta  = (const float*)d_in[10];
    float* out = (float*)d_out;

    float *qp, *kp, *vp, *cp, *yp;
    cudaGetSymbolAddress((void**)&qp, g_q);
    cudaGetSymbolAddress((void**)&kp, g_k);
    cudaGetSymbolAddress((void**)&vp, g_v);
    cudaGetSymbolAddress((void**)&cp, g_ctx);
    cudaGetSymbolAddress((void**)&yp, g_y);

    dim3 gemm_grid(DD / 64, MTOK / 64);   // (8, 128)
    gemm_xwt_kernel<<<gemm_grid, 256>>>(x, Wq, bq, nullptr, qp, MTOK, DD, DD);
    gemm_xwt_kernel<<<gemm_grid, 256>>>(x, Wk, bk, nullptr, kp, MTOK, DD, DD);
    gemm_xwt_kernel<<<gemm_grid, 256>>>(x, Wv, bv, nullptr, vp, MTOK, DD, DD);

    attn_kernel<<<dim3(SS / 64, BB * HH), 256>>>();

    gemm_xwt_kernel<<<gemm_grid, 256>>>(cp, Wo, bo, x, yp, MTOK, DD, DD);

    ln_kernel<<<MTOK, 128>>>(yp, gamma, beta, out);
}

// round 3
// speedup vs baseline: 2.6834x; 2.6834x over previous
#include <cuda_runtime.h>
#include <cstdint>

#define BB 4
#define SS 2048
#define DD 512
#define HH 8
#define MTOK (BB*SS)

// Scratch (module-load allocated; no cudaMalloc anywhere)
__device__ float g_q[MTOK*DD];
__device__ float g_k[MTOK*DD];
__device__ float g_v[MTOK*DD];
__device__ float g_ctx[MTOK*DD];
__device__ float g_y[MTOK*DD];

__device__ __forceinline__ uint32_t f2tf(float x) {
    uint32_t u; asm("cvt.rna.tf32.f32 %0, %1;" : "=r"(u) : "f"(x)); return u;
}

// D += A*B, m16n8k8 tf32 (sm_80 PTX -> Blackwell HMMA)
__device__ __forceinline__ void mma8(float* d, const uint32_t* a, const uint32_t* b) {
    asm volatile(
        "mma.sync.aligned.m16n8k8.row.col.f32.tf32.tf32.f32 "
        "{%0,%1,%2,%3}, {%4,%5,%6,%7}, {%8,%9}, {%0,%1,%2,%3};"
        : "+f"(d[0]), "+f"(d[1]), "+f"(d[2]), "+f"(d[3])
        : "r"(a[0]), "r"(a[1]), "r"(a[2]), "r"(a[3]), "r"(b[0]), "r"(b[1]));
}

// ============================================================================
// GEMM: C[m][n] = sum_k A[m][k]*W[n][k] + bias[n] (+res). Tile 64x128, BK=32.
// 8 warps as 2(m) x 4(n); warp tile 32x32 (2 mtiles x 4 ntiles).
// SMEM row stride 36 words (== 4 mod 32) -> conflict-free fragment loads.
// ============================================================================
__global__ __launch_bounds__(256) void gemm_mma(
    const float* __restrict__ A, const float* __restrict__ W,
    const float* __restrict__ bias, const float* __restrict__ res,
    float* __restrict__ C)
{
    __shared__ uint32_t As[64][36];
    __shared__ uint32_t Ws[128][36];
    const int tid = threadIdx.x, wid = tid >> 5, lane = tid & 31;
    const int g = lane >> 2, t = lane & 3;
    const int wm = wid >> 2, wn = wid & 3;
    const int m0 = blockIdx.y * 64, n0 = blockIdx.x * 128;

    float acc[2][4][4];
#pragma unroll
    for (int im = 0; im < 2; im++)
#pragma unroll
        for (int jn = 0; jn < 4; jn++)
#pragma unroll
            for (int e = 0; e < 4; e++) acc[im][jn][e] = 0.f;

    for (int ch = 0; ch < 16; ch++) {
        float4 av[2], wv[4];
#pragma unroll
        for (int it = 0; it < 2; it++) {
            const int i = tid + 256 * it, row = i >> 3, c4 = i & 7;
            av[it] = *(const float4*)(A + (size_t)(m0 + row) * 512 + ch * 32 + c4 * 4);
        }
#pragma unroll
        for (int it = 0; it < 4; it++) {
            const int i = tid + 256 * it, row = i >> 3, c4 = i & 7;
            wv[it] = *(const float4*)(W + (size_t)(n0 + row) * 512 + ch * 32 + c4 * 4);
        }
        __syncthreads();
#pragma unroll
        for (int it = 0; it < 2; it++) {
            const int i = tid + 256 * it, row = i >> 3, c4 = i & 7;
            uint4 u = { f2tf(av[it].x), f2tf(av[it].y), f2tf(av[it].z), f2tf(av[it].w) };
            *(uint4*)&As[row][c4 * 4] = u;
        }
#pragma unroll
        for (int it = 0; it < 4; it++) {
            const int i = tid + 256 * it, row = i >> 3, c4 = i & 7;
            uint4 u = { f2tf(wv[it].x), f2tf(wv[it].y), f2tf(wv[it].z), f2tf(wv[it].w) };
            *(uint4*)&Ws[row][c4 * 4] = u;
        }
        __syncthreads();

#pragma unroll
        for (int ks = 0; ks < 4; ks++) {
            uint32_t af[2][4];
#pragma unroll
            for (int im = 0; im < 2; im++) {
                const int r = wm * 32 + im * 16 + g, c = ks * 8 + t;
                af[im][0] = As[r][c];     af[im][1] = As[r + 8][c];
                af[im][2] = As[r][c + 4]; af[im][3] = As[r + 8][c + 4];
            }
#pragma unroll
            for (int jn = 0; jn < 4; jn++) {
                const int r = wn * 32 + jn * 8 + g, c = ks * 8 + t;
                uint32_t bf[2] = { Ws[r][c], Ws[r][c + 4] };
                mma8(acc[0][jn], af[0], bf);
                mma8(acc[1][jn], af[1], bf);
            }
        }
    }

#pragma unroll
    for (int im = 0; im < 2; im++) {
#pragma unroll
        for (int jn = 0; jn < 4; jn++) {
            const int row = m0 + wm * 32 + im * 16 + g;
            const int col = n0 + wn * 32 + jn * 8 + 2 * t;
            const float b0 = bias[col], b1 = bias[col + 1];
            float v0 = acc[im][jn][0] + b0, v1 = acc[im][jn][1] + b1;
            float v2 = acc[im][jn][2] + b0, v3 = acc[im][jn][3] + b1;
            if (res) {
                float2 r0 = *(const float2*)(res + (size_t)row * 512 + col);
                float2 r1 = *(const float2*)(res + (size_t)(row + 8) * 512 + col);
                v0 += r0.x; v1 += r0.y; v2 += r1.x; v3 += r1.y;
            }
            *(float2*)(C + (size_t)row * 512 + col)       = make_float2(v0, v1);
            *(float2*)(C + (size_t)(row + 8) * 512 + col) = make_float2(v2, v3);
        }
    }
}

// ============================================================================
// Flash attention, mma tf32. Per (b,h): 128 q-rows/block, 64 keys/iter.
// 8 warps; warp w owns q-rows [w*16, w*16+16) -> warp-local online softmax.
// Q lives in registers as A-fragments. P routed through per-warp SMEM strip.
// SMEM: Ps[128][68] (Q staging, then P), Ks[64][68], Vs[64][72].
// ============================================================================
#define AT_SMEM (34816 + 17408 + 18432)
__global__ __launch_bounds__(256) void attn_mma()
{
    extern __shared__ __align__(16) char sm[];
    uint32_t* Ps = (uint32_t*)sm;              // [128][68]
    uint32_t* Ks = (uint32_t*)(sm + 34816);    // [64][68]
    uint32_t* Vs = (uint32_t*)(sm + 52224);    // [64][72]

    const int tid = threadIdx.x, wid = tid >> 5, lane = tid & 31;
    const int g = lane >> 2, t = lane & 3;
    const int bh = blockIdx.y;
    const size_t base = (size_t)(bh >> 3) * SS * DD + (size_t)(bh & 7) * 64;
    const float* qp = g_q + base;
    const float* kp = g_k + base;
    const float* vp = g_v + base;
    float* op = g_ctx + base;
    const int q0 = blockIdx.x * 128;
    const int qr = wid * 16;

    // stage Q (scaled by 1/8) into Ps
#pragma unroll
    for (int it = 0; it < 8; it++) {
        const int i = tid + 256 * it, row = i >> 4, c4 = i & 15;
        float4 v = *(const float4*)(qp + (size_t)(q0 + row) * 512 + c4 * 4);
        uint4 u = { f2tf(v.x * 0.125f), f2tf(v.y * 0.125f),
                    f2tf(v.z * 0.125f), f2tf(v.w * 0.125f) };
        *(uint4*)&Ps[row * 68 + c4 * 4] = u;
    }
    __syncthreads();

    // Q fragments into registers
    uint32_t qf[8][4];
#pragma unroll
    for (int ks = 0; ks < 8; ks++) {
        const int c = ks * 8 + t;
        qf[ks][0] = Ps[(qr + g) * 68 + c];     qf[ks][1] = Ps[(qr + 8 + g) * 68 + c];
        qf[ks][2] = Ps[(qr + g) * 68 + c + 4]; qf[ks][3] = Ps[(qr + 8 + g) * 68 + c + 4];
    }

    float oacc[8][4];
#pragma unroll
    for (int j = 0; j < 8; j++)
#pragma unroll
        for (int e = 0; e < 4; e++) oacc[j][e] = 0.f;
    float m0r = -1e30f, m1r = -1e30f, l0 = 0.f, l1 = 0.f;

    for (int kb = 0; kb < SS / 64; kb++) {
        // prefetch K/V tile into registers
        float4 kv[4], vv[4];
#pragma unroll
        for (int it = 0; it < 4; it++) {
            const int i = tid + 256 * it, row = i >> 4, c4 = i & 15;
            kv[it] = *(const float4*)(kp + (size_t)(kb * 64 + row) * 512 + c4 * 4);
            vv[it] = *(const float4*)(vp + (size_t)(kb * 64 + row) * 512 + c4 * 4);
        }
        __syncthreads();   // previous-iter Ks/Vs reads complete
#pragma unroll
        for (int it = 0; it < 4; it++) {
            const int i = tid + 256 * it, row = i >> 4, c4 = i & 15;
            uint4 uk = { f2tf(kv[it].x), f2tf(kv[it].y), f2tf(kv[it].z), f2tf(kv[it].w) };
            *(uint4*)&Ks[row * 68 + c4 * 4] = uk;
            uint4 uv = { f2tf(vv[it].x), f2tf(vv[it].y), f2tf(vv[it].z), f2tf(vv[it].w) };
            *(uint4*)&Vs[row * 72 + c4 * 4] = uv;
        }
        __syncthreads();

        // S = Q . K^T  (16 x 64 per warp)
        float sacc[8][4];
#pragma unroll
        for (int j = 0; j < 8; j++)
#pragma unroll
            for (int e = 0; e < 4; e++) sacc[j][e] = 0.f;
#pragma unroll
        for (int ks = 0; ks < 8; ks++) {
            const int c = ks * 8 + t;
#pragma unroll
            for (int jn = 0; jn < 8; jn++) {
                const int r = jn * 8 + g;
                uint32_t bf[2] = { Ks[r * 68 + c], Ks[r * 68 + c + 4] };
                mma8(sacc[jn], qf[ks], bf);
            }
        }

        // warp-local online softmax; rows r0 = qr+g, r1 = qr+8+g
        float mx0 = -1e30f, mx1 = -1e30f;
#pragma unroll
        for (int jn = 0; jn < 8; jn++) {
            mx0 = fmaxf(mx0, fmaxf(sacc[jn][0], sacc[jn][1]));
            mx1 = fmaxf(mx1, fmaxf(sacc[jn][2], sacc[jn][3]));
        }
        mx0 = fmaxf(mx0, __shfl_xor_sync(0xffffffffu, mx0, 1));
        mx0 = fmaxf(mx0, __shfl_xor_sync(0xffffffffu, mx0, 2));
        mx1 = fmaxf(mx1, __shfl_xor_sync(0xffffffffu, mx1, 1));
        mx1 = fmaxf(mx1, __shfl_xor_sync(0xffffffffu, mx1, 2));
        const float mn0 = fmaxf(m0r, mx0), mn1 = fmaxf(m1r, mx1);
        const float c0 = __expf(m0r - mn0), c1 = __expf(m1r - mn1);

        float s0 = 0.f, s1 = 0.f;
#pragma unroll
        for (int jn = 0; jn < 8; jn++) {
            const float p00 = __expf(sacc[jn][0] - mn0);
            const float p01 = __expf(sacc[jn][1] - mn0);
            const float p10 = __expf(sacc[jn][2] - mn1);
            const float p11 = __expf(sacc[jn][3] - mn1);
            s0 += p00 + p01; s1 += p10 + p11;
            const int cidx = jn * 8 + 2 * t;
            Ps[(qr + g) * 68 + cidx]         = f2tf(p00);
            Ps[(qr + g) * 68 + cidx + 1]     = f2tf(p01);
            Ps[(qr + 8 + g) * 68 + cidx]     = f2tf(p10);
            Ps[(qr + 8 + g) * 68 + cidx + 1] = f2tf(p11);
        }
        s0 += __shfl_xor_sync(0xffffffffu, s0, 1);
        s0 += __shfl_xor_sync(0xffffffffu, s0, 2);
        s1 += __shfl_xor_sync(0xffffffffu, s1, 1);
        s1 += __shfl_xor_sync(0xffffffffu, s1, 2);
        l0 = l0 * c0 + s0; l1 = l1 * c1 + s1;
        m0r = mn0; m1r = mn1;
#pragma unroll
        for (int jd = 0; jd < 8; jd++) {
            oacc[jd][0] *= c0; oacc[jd][1] *= c0;
            oacc[jd][2] *= c1; oacc[jd][3] *= c1;
        }
        __syncwarp();

        // O += P . V  (V as [key][d], stride 72 == 8 mod 32 -> conflict-free)
#pragma unroll
        for (int ks = 0; ks < 8; ks++) {
            const int c = ks * 8 + t;
            uint32_t pf[4] = { Ps[(qr + g) * 68 + c],     Ps[(qr + 8 + g) * 68 + c],
                               Ps[(qr + g) * 68 + c + 4], Ps[(qr + 8 + g) * 68 + c + 4] };
#pragma unroll
            for (int jd = 0; jd < 8; jd++) {
                const int dcol = jd * 8 + g;
                uint32_t bf[2] = { Vs[(ks * 8 + t) * 72 + dcol],
                                   Vs[(ks * 8 + t + 4) * 72 + dcol] };
                mma8(oacc[jd], pf, bf);
            }
        }
    }

    const float inv0 = 1.f / l0, inv1 = 1.f / l1;
#pragma unroll
    for (int jd = 0; jd < 8; jd++) {
        const int col = jd * 8 + 2 * t;
        *(float2*)(op + (size_t)(q0 + qr + g) * 512 + col) =
            make_float2(oacc[jd][0] * inv0, oacc[jd][1] * inv0);
        *(float2*)(op + (size_t)(q0 + qr + 8 + g) * 512 + col) =
            make_float2(oacc[jd][2] * inv1, oacc[jd][3] * inv1);
    }
}

// ============================================================================
// LayerNorm: one block (128 thr) per token row of 512
// ============================================================================
__global__ __launch_bounds__(128) void ln_kernel(
    const float* __restrict__ y, const float* __restrict__ gamma,
    const float* __restrict__ beta, float* __restrict__ out)
{
    const int row = blockIdx.x;
    const float* yr = y + (size_t)row * DD;
    float v[4], s = 0.f, s2 = 0.f;
#pragma unroll
    for (int i = 0; i < 4; i++) {
        float x = yr[threadIdx.x + i * 128];
        v[i] = x; s += x; s2 += x * x;
    }
#pragma unroll
    for (int o = 16; o; o >>= 1) {
        s  += __shfl_xor_sync(0xffffffffu, s, o);
        s2 += __shfl_xor_sync(0xffffffffu, s2, o);
    }
    __shared__ float sh[8];
    const int w = threadIdx.x >> 5;
    if ((threadIdx.x & 31) == 0) { sh[w] = s; sh[w + 4] = s2; }
    __syncthreads();
    s  = sh[0] + sh[1] + sh[2] + sh[3];
    s2 = sh[4] + sh[5] + sh[6] + sh[7];
    const float mu   = s * (1.f / DD);
    const float var  = s2 * (1.f / DD) - mu * mu;
    const float rstd = rsqrtf(var + 1e-5f);
    float* orow = out + (size_t)row * DD;
#pragma unroll
    for (int i = 0; i < 4; i++) {
        const int c = threadIdx.x + i * 128;
        orow[c] = (v[i] - mu) * rstd * gamma[c] + beta[c];
    }
}

// ============================================================================
extern "C" void kernel_launch(void* const* d_in, const int* in_sizes, int n_in,
                              void* d_out, int out_size)
{
    const float* x     = (const float*)d_in[0];
    const float* Wq    = (const float*)d_in[1];
    const float* bq    = (const float*)d_in[2];
    const float* Wk    = (const float*)d_in[3];
    const float* bk    = (const float*)d_in[4];
    const float* Wv    = (const float*)d_in[5];
    const float* bv    = (const float*)d_in[6];
    const float* Wo    = (const float*)d_in[7];
    const float* bo    = (const float*)d_in[8];
    const float* gamma = (const float*)d_in[9];
    const float* beta  = (const float*)d_in[10];
    float* out = (float*)d_out;

    float *qp, *kp, *vp, *cp, *yp;
    cudaGetSymbolAddress((void**)&qp, g_q);
    cudaGetSymbolAddress((void**)&kp, g_k);
    cudaGetSymbolAddress((void**)&vp, g_v);
    cudaGetSymbolAddress((void**)&cp, g_ctx);
    cudaGetSymbolAddress((void**)&yp, g_y);

    cudaFuncSetAttribute(attn_mma, cudaFuncAttributeMaxDynamicSharedMemorySize, AT_SMEM);

    dim3 gg(4, 128);   // N/128, M/64
    gemm_mma<<<gg, 256>>>(x, Wq, bq, nullptr, qp);
    gemm_mma<<<gg, 256>>>(x, Wk, bk, nullptr, kp);
    gemm_mma<<<gg, 256>>>(x, Wv, bv, nullptr, vp);

    attn_mma<<<dim3(SS / 128, BB * HH), 256, AT_SMEM>>>();

    gemm_mma<<<gg, 256>>>(cp, Wo, bo, x, yp);

    ln_kernel<<<MTOK, 128>>>(yp, gamma, beta, out);
}

// round 4
// speedup vs baseline: 2.7696x; 1.0321x over previous
#include <cuda_runtime.h>
#include <cstdint>

#define BB 4
#define SS 2048
#define DD 512
#define HH 8
#define MTOK (BB*SS)

// Scratch (module-load allocated; no cudaMalloc anywhere)
__device__ float g_q[MTOK*DD];
__device__ float g_k[MTOK*DD];
__device__ float g_v[MTOK*DD];
__device__ float g_ctx[MTOK*DD];
__device__ float g_y[MTOK*DD];

__device__ __forceinline__ uint32_t f2tf(float x) {
    uint32_t u; asm("cvt.rna.tf32.f32 %0, %1;" : "=r"(u) : "f"(x)); return u;
}

// D += A*B, m16n8k8 tf32 (sm_80 PTX -> Blackwell HMMA)
__device__ __forceinline__ void mma8(float* d, const uint32_t* a, const uint32_t* b) {
    asm volatile(
        "mma.sync.aligned.m16n8k8.row.col.f32.tf32.tf32.f32 "
        "{%0,%1,%2,%3}, {%4,%5,%6,%7}, {%8,%9}, {%0,%1,%2,%3};"
        : "+f"(d[0]), "+f"(d[1]), "+f"(d[2]), "+f"(d[3])
        : "r"(a[0]), "r"(a[1]), "r"(a[2]), "r"(a[3]), "r"(b[0]), "r"(b[1]));
}

// ============================================================================
// GEMM: C[m][n] = sum_k A[m][k]*W[n][k] + bias[n] (+res). Tile 64x128, BK=32.
// 8 warps as 2(m) x 4(n); warp tile 32x32 (2 mtiles x 4 ntiles).
// SMEM row stride 36 words (== 4 mod 32) -> conflict-free fragment loads.
// ============================================================================
__global__ __launch_bounds__(256) void gemm_mma(
    const float* __restrict__ A, const float* __restrict__ W,
    const float* __restrict__ bias, const float* __restrict__ res,
    float* __restrict__ C)
{
    __shared__ uint32_t As[64][36];
    __shared__ uint32_t Ws[128][36];
    const int tid = threadIdx.x, wid = tid >> 5, lane = tid & 31;
    const int g = lane >> 2, t = lane & 3;
    const int wm = wid >> 2, wn = wid & 3;
    const int m0 = blockIdx.y * 64, n0 = blockIdx.x * 128;

    float acc[2][4][4];
#pragma unroll
    for (int im = 0; im < 2; im++)
#pragma unroll
        for (int jn = 0; jn < 4; jn++)
#pragma unroll
            for (int e = 0; e < 4; e++) acc[im][jn][e] = 0.f;

    for (int ch = 0; ch < 16; ch++) {
        float4 av[2], wv[4];
#pragma unroll
        for (int it = 0; it < 2; it++) {
            const int i = tid + 256 * it, row = i >> 3, c4 = i & 7;
            av[it] = *(const float4*)(A + (size_t)(m0 + row) * 512 + ch * 32 + c4 * 4);
        }
#pragma unroll
        for (int it = 0; it < 4; it++) {
            const int i = tid + 256 * it, row = i >> 3, c4 = i & 7;
            wv[it] = *(const float4*)(W + (size_t)(n0 + row) * 512 + ch * 32 + c4 * 4);
        }
        __syncthreads();
#pragma unroll
        for (int it = 0; it < 2; it++) {
            const int i = tid + 256 * it, row = i >> 3, c4 = i & 7;
            uint4 u = { f2tf(av[it].x), f2tf(av[it].y), f2tf(av[it].z), f2tf(av[it].w) };
            *(uint4*)&As[row][c4 * 4] = u;
        }
#pragma unroll
        for (int it = 0; it < 4; it++) {
            const int i = tid + 256 * it, row = i >> 3, c4 = i & 7;
            uint4 u = { f2tf(wv[it].x), f2tf(wv[it].y), f2tf(wv[it].z), f2tf(wv[it].w) };
            *(uint4*)&Ws[row][c4 * 4] = u;
        }
        __syncthreads();

#pragma unroll
        for (int ks = 0; ks < 4; ks++) {
            uint32_t af[2][4];
#pragma unroll
            for (int im = 0; im < 2; im++) {
                const int r = wm * 32 + im * 16 + g, c = ks * 8 + t;
                af[im][0] = As[r][c];     af[im][1] = As[r + 8][c];
                af[im][2] = As[r][c + 4]; af[im][3] = As[r + 8][c + 4];
            }
#pragma unroll
            for (int jn = 0; jn < 4; jn++) {
                const int r = wn * 32 + jn * 8 + g, c = ks * 8 + t;
                uint32_t bf[2] = { Ws[r][c], Ws[r][c + 4] };
                mma8(acc[0][jn], af[0], bf);
                mma8(acc[1][jn], af[1], bf);
            }
        }
    }

#pragma unroll
    for (int im = 0; im < 2; im++) {
#pragma unroll
        for (int jn = 0; jn < 4; jn++) {
            const int row = m0 + wm * 32 + im * 16 + g;
            const int col = n0 + wn * 32 + jn * 8 + 2 * t;
            const float b0 = bias[col], b1 = bias[col + 1];
            float v0 = acc[im][jn][0] + b0, v1 = acc[im][jn][1] + b1;
            float v2 = acc[im][jn][2] + b0, v3 = acc[im][jn][3] + b1;
            if (res) {
                float2 r0 = *(const float2*)(res + (size_t)row * 512 + col);
                float2 r1 = *(const float2*)(res + (size_t)(row + 8) * 512 + col);
                v0 += r0.x; v1 += r0.y; v2 += r1.x; v3 += r1.y;
            }
            *(float2*)(C + (size_t)row * 512 + col)       = make_float2(v0, v1);
            *(float2*)(C + (size_t)(row + 8) * 512 + col) = make_float2(v2, v3);
        }
    }
}

// ============================================================================
// Flash attention, mma tf32. Per (b,h): 128 q-rows/block, 64 keys/iter.
// 8 warps; warp w owns q-rows [w*16, w*16+16) -> warp-local online softmax.
// K/V double-buffered in SMEM: ONE __syncthreads per iteration; next tile's
// LDG issued before current tile's MMAs so memory latency hides under compute.
// __launch_bounds__(256,2) caps regs at 128 -> 2 CTAs/SM (vs 1 before).
// SMEM: Ps[128][68] (Q staging, then P), Ks[2][64][68], Vs[2][64][72].
// ============================================================================
#define PS_W   (34816/4)
#define KS_W   (17408/4)
#define VS_W   (18432/4)
#define AT_SMEM (34816 + 2*17408 + 2*18432)   // 106496 B
__global__ __launch_bounds__(256, 2) void attn_mma()
{
    extern __shared__ __align__(16) char sm[];
    uint32_t* Ps = (uint32_t*)sm;                        // [128][68]
    uint32_t* Kb = (uint32_t*)(sm + 34816);              // [2][64][68]
    uint32_t* Vb = (uint32_t*)(sm + 34816 + 2*17408);    // [2][64][72]

    const int tid = threadIdx.x, wid = tid >> 5, lane = tid & 31;
    const int g = lane >> 2, t = lane & 3;
    const int bh = blockIdx.y;
    const size_t base = (size_t)(bh >> 3) * SS * DD + (size_t)(bh & 7) * 64;
    const float* qp = g_q + base;
    const float* kp = g_k + base;
    const float* vp = g_v + base;
    float* op = g_ctx + base;
    const int q0 = blockIdx.x * 128;
    const int qr = wid * 16;

    const int ldrow = tid >> 4, ldc4 = tid & 15;   // K/V tile loads: 64 rows x 16 f4

    // ---- prologue: stage Q (scaled 1/8) into Ps; load K0/V0 into buffer 0 ----
#pragma unroll
    for (int it = 0; it < 8; it++) {
        const int i = tid + 256 * it, row = i >> 4, c4 = i & 15;
        float4 v = *(const float4*)(qp + (size_t)(q0 + row) * 512 + c4 * 4);
        uint4 u = { f2tf(v.x * 0.125f), f2tf(v.y * 0.125f),
                    f2tf(v.z * 0.125f), f2tf(v.w * 0.125f) };
        *(uint4*)&Ps[row * 68 + c4 * 4] = u;
    }
#pragma unroll
    for (int it = 0; it < 4; it++) {
        const int i = tid + 256 * it, row = i >> 4, c4 = i & 15;
        float4 k4 = *(const float4*)(kp + (size_t)row * 512 + c4 * 4);
        float4 v4 = *(const float4*)(vp + (size_t)row * 512 + c4 * 4);
        uint4 uk = { f2tf(k4.x), f2tf(k4.y), f2tf(k4.z), f2tf(k4.w) };
        *(uint4*)&Kb[row * 68 + c4 * 4] = uk;
        uint4 uv = { f2tf(v4.x), f2tf(v4.y), f2tf(v4.z), f2tf(v4.w) };
        *(uint4*)&Vb[row * 72 + c4 * 4] = uv;
    }
    __syncthreads();

    // Q fragments into registers
    uint32_t qf[8][4];
#pragma unroll
    for (int ks = 0; ks < 8; ks++) {
        const int c = ks * 8 + t;
        qf[ks][0] = Ps[(qr + g) * 68 + c];     qf[ks][1] = Ps[(qr + 8 + g) * 68 + c];
        qf[ks][2] = Ps[(qr + g) * 68 + c + 4]; qf[ks][3] = Ps[(qr + 8 + g) * 68 + c + 4];
    }

    float oacc[8][4];
#pragma unroll
    for (int j = 0; j < 8; j++)
#pragma unroll
        for (int e = 0; e < 4; e++) oacc[j][e] = 0.f;
    float m0r = -1e30f, m1r = -1e30f, l0 = 0.f, l1 = 0.f;

    for (int kb = 0; kb < SS / 64; kb++) {
        const uint32_t* Kc = Kb + (kb & 1) * KS_W;
        const uint32_t* Vc = Vb + (kb & 1) * VS_W;
        uint32_t* Kn = Kb + ((kb & 1) ^ 1) * KS_W;
        uint32_t* Vn = Vb + ((kb & 1) ^ 1) * VS_W;
        const bool more = (kb + 1) < SS / 64;

        // prefetch next K tile (regs live through the S phase)
        float4 kr[4];
        if (more) {
            const float* src = kp + (size_t)((kb + 1) * 64 + ldrow) * 512 + ldc4 * 4;
#pragma unroll
            for (int it = 0; it < 4; it++)
                kr[it] = *(const float4*)(src + (size_t)(16 * it) * 512);
        }

        // ---- S = Q . K^T (16 x 64 per warp) ----
        float sacc[8][4];
#pragma unroll
        for (int j = 0; j < 8; j++)
#pragma unroll
            for (int e = 0; e < 4; e++) sacc[j][e] = 0.f;
#pragma unroll
        for (int ks = 0; ks < 8; ks++) {
            const int c = ks * 8 + t;
#pragma unroll
            for (int jn = 0; jn < 8; jn++) {
                const int r = jn * 8 + g;
                uint32_t bf[2] = { Kc[r * 68 + c], Kc[r * 68 + c + 4] };
                mma8(sacc[jn], qf[ks], bf);
            }
        }

        // ---- warp-local online softmax; rows r0 = qr+g, r1 = qr+8+g ----
        float mx0 = -1e30f, mx1 = -1e30f;
#pragma unroll
        for (int jn = 0; jn < 8; jn++) {
            mx0 = fmaxf(mx0, fmaxf(sacc[jn][0], sacc[jn][1]));
            mx1 = fmaxf(mx1, fmaxf(sacc[jn][2], sacc[jn][3]));
        }
        mx0 = fmaxf(mx0, __shfl_xor_sync(0xffffffffu, mx0, 1));
        mx0 = fmaxf(mx0, __shfl_xor_sync(0xffffffffu, mx0, 2));
        mx1 = fmaxf(mx1, __shfl_xor_sync(0xffffffffu, mx1, 1));
        mx1 = fmaxf(mx1, __shfl_xor_sync(0xffffffffu, mx1, 2));
        const float mn0 = fmaxf(m0r, mx0), mn1 = fmaxf(m1r, mx1);
        const float c0 = __expf(m0r - mn0), c1 = __expf(m1r - mn1);

        float s0 = 0.f, s1 = 0.f;
#pragma unroll
        for (int jn = 0; jn < 8; jn++) {
            const float p00 = __expf(sacc[jn][0] - mn0);
            const float p01 = __expf(sacc[jn][1] - mn0);
            const float p10 = __expf(sacc[jn][2] - mn1);
            const float p11 = __expf(sacc[jn][3] - mn1);
            s0 += p00 + p01; s1 += p10 + p11;
            const int cidx = jn * 8 + 2 * t;
            Ps[(qr + g) * 68 + cidx]         = f2tf(p00);
            Ps[(qr + g) * 68 + cidx + 1]     = f2tf(p01);
            Ps[(qr + 8 + g) * 68 + cidx]     = f2tf(p10);
            Ps[(qr + 8 + g) * 68 + cidx + 1] = f2tf(p11);
        }
        s0 += __shfl_xor_sync(0xffffffffu, s0, 1);
        s0 += __shfl_xor_sync(0xffffffffu, s0, 2);
        s1 += __shfl_xor_sync(0xffffffffu, s1, 1);
        s1 += __shfl_xor_sync(0xffffffffu, s1, 2);
        l0 = l0 * c0 + s0; l1 = l1 * c1 + s1;
        m0r = mn0; m1r = mn1;
#pragma unroll
        for (int jd = 0; jd < 8; jd++) {
            oacc[jd][0] *= c0; oacc[jd][1] *= c0;
            oacc[jd][2] *= c1; oacc[jd][3] *= c1;
        }
        __syncwarp();

        // retire K prefetch into the other buffer; prefetch next V tile
        if (more) {
#pragma unroll
            for (int it = 0; it < 4; it++) {
                uint4 u = { f2tf(kr[it].x), f2tf(kr[it].y), f2tf(kr[it].z), f2tf(kr[it].w) };
                *(uint4*)&Kn[(16 * it + ldrow) * 68 + ldc4 * 4] = u;
            }
        }
        float4 vr[4];
        if (more) {
            const float* src = vp + (size_t)((kb + 1) * 64 + ldrow) * 512 + ldc4 * 4;
#pragma unroll
            for (int it = 0; it < 4; it++)
                vr[it] = *(const float4*)(src + (size_t)(16 * it) * 512);
        }

        // ---- O += P . V ----
#pragma unroll
        for (int ks = 0; ks < 8; ks++) {
            const int c = ks * 8 + t;
            uint32_t pf[4] = { Ps[(qr + g) * 68 + c],     Ps[(qr + 8 + g) * 68 + c],
                               Ps[(qr + g) * 68 + c + 4], Ps[(qr + 8 + g) * 68 + c + 4] };
#pragma unroll
            for (int jd = 0; jd < 8; jd++) {
                const int dcol = jd * 8 + g;
                uint32_t bf[2] = { Vc[(ks * 8 + t) * 72 + dcol],
                                   Vc[(ks * 8 + t + 4) * 72 + dcol] };
                mma8(oacc[jd], pf, bf);
            }
        }

        if (more) {
#pragma unroll
            for (int it = 0; it < 4; it++) {
                uint4 u = { f2tf(vr[it].x), f2tf(vr[it].y), f2tf(vr[it].z), f2tf(vr[it].w) };
                *(uint4*)&Vn[(16 * it + ldrow) * 72 + ldc4 * 4] = u;
            }
        }
        __syncthreads();
    }

    const float inv0 = 1.f / l0, inv1 = 1.f / l1;
#pragma unroll
    for (int jd = 0; jd < 8; jd++) {
        const int col = jd * 8 + 2 * t;
        *(float2*)(op + (size_t)(q0 + qr + g) * 512 + col) =
            make_float2(oacc[jd][0] * inv0, oacc[jd][1] * inv0);
        *(float2*)(op + (size_t)(q0 + qr + 8 + g) * 512 + col) =
            make_float2(oacc[jd][2] * inv1, oacc[jd][3] * inv1);
    }
}

// ============================================================================
// LayerNorm: one block (128 thr) per token row of 512
// ============================================================================
__global__ __launch_bounds__(128) void ln_kernel(
    const float* __restrict__ y, const float* __restrict__ gamma,
    const float* __restrict__ beta, float* __restrict__ out)
{
    const int row = blockIdx.x;
    const float* yr = y + (size_t)row * DD;
    float v[4], s = 0.f, s2 = 0.f;
#pragma unroll
    for (int i = 0; i < 4; i++) {
        float x = yr[threadIdx.x + i * 128];
        v[i] = x; s += x; s2 += x * x;
    }
#pragma unroll
    for (int o = 16; o; o >>= 1) {
        s  += __shfl_xor_sync(0xffffffffu, s, o);
        s2 += __shfl_xor_sync(0xffffffffu, s2, o);
    }
    __shared__ float sh[8];
    const int w = threadIdx.x >> 5;
    if ((threadIdx.x & 31) == 0) { sh[w] = s; sh[w + 4] = s2; }
    __syncthreads();
    s  = sh[0] + sh[1] + sh[2] + sh[3];
    s2 = sh[4] + sh[5] + sh[6] + sh[7];
    const float mu   = s * (1.f / DD);
    const float var  = s2 * (1.f / DD) - mu * mu;
    const float rstd = rsqrtf(var + 1e-5f);
    float* orow = out + (size_t)row * DD;
#pragma unroll
    for (int i = 0; i < 4; i++) {
        const int c = threadIdx.x + i * 128;
        orow[c] = (v[i] - mu) * rstd * gamma[c] + beta[c];
    }
}

// ============================================================================
extern "C" void kernel_launch(void* const* d_in, const int* in_sizes, int n_in,
                              void* d_out, int out_size)
{
    const float* x     = (const float*)d_in[0];
    const float* Wq    = (const float*)d_in[1];
    const float* bq    = (const float*)d_in[2];
    const float* Wk    = (const float*)d_in[3];
    const float* bk    = (const float*)d_in[4];
    const float* Wv    = (const float*)d_in[5];
    const float* bv    = (const float*)d_in[6];
    const float* Wo    = (const float*)d_in[7];
    const float* bo    = (const float*)d_in[8];
    const float* gamma = (const float*)d_in[9];
    const float* beta  = (const float*)d_in[10];
    float* out = (float*)d_out;

    float *qp, *kp, *vp, *cp, *yp;
    cudaGetSymbolAddress((void**)&qp, g_q);
    cudaGetSymbolAddress((void**)&kp, g_k);
    cudaGetSymbolAddress((void**)&vp, g_v);
    cudaGetSymbolAddress((void**)&cp, g_ctx);
    cudaGetSymbolAddress((void**)&yp, g_y);

    cudaFuncSetAttribute(attn_mma, cudaFuncAttributeMaxDynamicSharedMemorySize, AT_SMEM);

    dim3 gg(4, 128);   // N/128, M/64
    gemm_mma<<<gg, 256>>>(x, Wq, bq, nullptr, qp);
    gemm_mma<<<gg, 256>>>(x, Wk, bk, nullptr, kp);
    gemm_mma<<<gg, 256>>>(x, Wv, bv, nullptr, vp);

    attn_mma<<<dim3(SS / 128, BB * HH), 256, AT_SMEM>>>();

    gemm_mma<<<gg, 256>>>(cp, Wo, bo, x, yp);

    ln_kernel<<<MTOK, 128>>>(yp, gamma, beta, out);
}

// round 6
// speedup vs baseline: 4.4259x; 1.5980x over previous
#include <cuda_runtime.h>
#include <cuda_bf16.h>
#include <cstdint>

#define BB 4
#define SS 2048
#define DD 512
#define HH 8
#define MTOK (BB*SS)
#define QSCALE (0.125f * 1.44269504f)   // 1/sqrt(dk) * log2(e)

// Scratch (module-load allocated; no cudaMalloc anywhere)
__device__ __align__(256) __nv_bfloat16 g_q[MTOK*DD];
__device__ __align__(256) __nv_bfloat16 g_k[MTOK*DD];
__device__ __align__(256) __nv_bfloat16 g_v[MTOK*DD];
__device__ float g_ctx[MTOK*DD];
__device__ float g_y[MTOK*DD];

// ======================= helpers ===========================================
__device__ __forceinline__ uint32_t f2tf(float x) {
    uint32_t u; asm("cvt.rna.tf32.f32 %0, %1;" : "=r"(u) : "f"(x)); return u;
}
__device__ __forceinline__ uint32_t pk(float lo, float hi) {
    uint32_t r; asm("cvt.rn.bf16x2.f32 %0, %1, %2;" : "=r"(r) : "f"(hi), "f"(lo)); return r;
}
__device__ __forceinline__ float ex2(float x) {
    float r; asm("ex2.approx.f32 %0, %1;" : "=f"(r) : "f"(x)); return r;
}
__device__ __forceinline__ uint32_t smem_u32(const void* p) {
    uint32_t a;
    asm("{ .reg .u64 t; cvta.to.shared.u64 t, %1; cvt.u32.u64 %0, t; }" : "=r"(a) : "l"(p));
    return a;
}
// tf32 m16n8k8 (projection GEMMs)
__device__ __forceinline__ void mma8(float* d, const uint32_t* a, const uint32_t* b) {
    asm volatile(
        "mma.sync.aligned.m16n8k8.row.col.f32.tf32.tf32.f32 "
        "{%0,%1,%2,%3}, {%4,%5,%6,%7}, {%8,%9}, {%0,%1,%2,%3};"
        : "+f"(d[0]), "+f"(d[1]), "+f"(d[2]), "+f"(d[3])
        : "r"(a[0]), "r"(a[1]), "r"(a[2]), "r"(a[3]), "r"(b[0]), "r"(b[1]));
}
// bf16 m16n8k16 (attention)
__device__ __forceinline__ void mma16(float* d, const uint32_t* a, const uint32_t* b) {
    asm volatile(
        "mma.sync.aligned.m16n8k16.row.col.f32.bf16.bf16.f32 "
        "{%0,%1,%2,%3}, {%4,%5,%6,%7}, {%8,%9}, {%0,%1,%2,%3};"
        : "+f"(d[0]), "+f"(d[1]), "+f"(d[2]), "+f"(d[3])
        : "r"(a[0]), "r"(a[1]), "r"(a[2]), "r"(a[3]), "r"(b[0]), "r"(b[1]));
}
__device__ __forceinline__ void ldsm4(uint32_t* r, uint32_t addr) {
    asm volatile("ldmatrix.sync.aligned.m8n8.x4.shared.b16 {%0,%1,%2,%3}, [%4];"
        : "=r"(r[0]), "=r"(r[1]), "=r"(r[2]), "=r"(r[3]) : "r"(addr));
}
__device__ __forceinline__ void ldsm4t(uint32_t* r, uint32_t addr) {
    asm volatile("ldmatrix.sync.aligned.m8n8.x4.trans.shared.b16 {%0,%1,%2,%3}, [%4];"
        : "=r"(r[0]), "=r"(r[1]), "=r"(r[2]), "=r"(r[3]) : "r"(addr));
}
__device__ __forceinline__ void cpa(uint32_t dst, const void* src) {
    asm volatile("cp.async.ca.shared.global [%0], [%1], 16;" :: "r"(dst), "l"(src) : "memory");
}
#define CP_COMMIT() asm volatile("cp.async.commit_group;" ::: "memory")
#define CP_WAIT(n)  asm volatile("cp.async.wait_group %0;" :: "n"(n) : "memory")

// ============================================================================
// tf32 GEMM mainloop (shared by both epilogues). Tile 64x128, BK=32,
// 8 warps 2x4; fills acc[2][4][4] for warp tile 32x32.
// ============================================================================
struct GemmCtx { int m0, n0, wm, wn, g, t; };

__device__ __forceinline__ void gemm_mainloop(
    const float* __restrict__ A, const float* __restrict__ W,
    uint32_t (*As)[36], uint32_t (*Ws)[36],
    const GemmCtx& cx, float acc[2][4][4])
{
    const int tid = threadIdx.x;
#pragma unroll
    for (int im = 0; im < 2; im++)
#pragma unroll
        for (int jn = 0; jn < 4; jn++)
#pragma unroll
            for (int e = 0; e < 4; e++) acc[im][jn][e] = 0.f;

    for (int ch = 0; ch < 16; ch++) {
        float4 av[2], wv[4];
#pragma unroll
        for (int it = 0; it < 2; it++) {
            const int i = tid + 256 * it, row = i >> 3, c4 = i & 7;
            av[it] = *(const float4*)(A + (size_t)(cx.m0 + row) * 512 + ch * 32 + c4 * 4);
        }
#pragma unroll
        for (int it = 0; it < 4; it++) {
            const int i = tid + 256 * it, row = i >> 3, c4 = i & 7;
            wv[it] = *(const float4*)(W + (size_t)(cx.n0 + row) * 512 + ch * 32 + c4 * 4);
        }
        __syncthreads();
#pragma unroll
        for (int it = 0; it < 2; it++) {
            const int i = tid + 256 * it, row = i >> 3, c4 = i & 7;
            uint4 u = { f2tf(av[it].x), f2tf(av[it].y), f2tf(av[it].z), f2tf(av[it].w) };
            *(uint4*)&As[row][c4 * 4] = u;
        }
#pragma unroll
        for (int it = 0; it < 4; it++) {
            const int i = tid + 256 * it, row = i >> 3, c4 = i & 7;
            uint4 u = { f2tf(wv[it].x), f2tf(wv[it].y), f2tf(wv[it].z), f2tf(wv[it].w) };
            *(uint4*)&Ws[row][c4 * 4] = u;
        }
        __syncthreads();

#pragma unroll
        for (int ks = 0; ks < 4; ks++) {
            uint32_t af[2][4];
#pragma unroll
            for (int im = 0; im < 2; im++) {
                const int r = cx.wm * 32 + im * 16 + cx.g, c = ks * 8 + cx.t;
                af[im][0] = As[r][c];     af[im][1] = As[r + 8][c];
                af[im][2] = As[r][c + 4]; af[im][3] = As[r + 8][c + 4];
            }
#pragma unroll
            for (int jn = 0; jn < 4; jn++) {
                const int r = cx.wn * 32 + jn * 8 + cx.g, c = ks * 8 + cx.t;
                uint32_t bf[2] = { Ws[r][c], Ws[r][c + 4] };
                mma8(acc[0][jn], af[0], bf);
                mma8(acc[1][jn], af[1], bf);
            }
        }
    }
}

__global__ __launch_bounds__(256) void gemm_mma(
    const float* __restrict__ A, const float* __restrict__ W,
    const float* __restrict__ bias, const float* __restrict__ res,
    float* __restrict__ C)
{
    __shared__ uint32_t As[64][36];
    __shared__ uint32_t Ws[128][36];
    const int tid = threadIdx.x, wid = tid >> 5, lane = tid & 31;
    GemmCtx cx;
    cx.g = lane >> 2; cx.t = lane & 3;
    cx.wm = wid >> 2; cx.wn = wid & 3;
    cx.m0 = blockIdx.y * 64; cx.n0 = blockIdx.x * 128;
    float acc[2][4][4];
    gemm_mainloop(A, W, As, Ws, cx, acc);

#pragma unroll
    for (int im = 0; im < 2; im++) {
#pragma unroll
        for (int jn = 0; jn < 4; jn++) {
            const int row = cx.m0 + cx.wm * 32 + im * 16 + cx.g;
            const int col = cx.n0 + cx.wn * 32 + jn * 8 + 2 * cx.t;
            const float b0 = bias[col], b1 = bias[col + 1];
            float v0 = acc[im][jn][0] + b0, v1 = acc[im][jn][1] + b1;
            float v2 = acc[im][jn][2] + b0, v3 = acc[im][jn][3] + b1;
            if (res) {
                float2 r0 = *(const float2*)(res + (size_t)row * 512 + col);
                float2 r1 = *(const float2*)(res + (size_t)(row + 8) * 512 + col);
                v0 += r0.x; v1 += r0.y; v2 += r1.x; v3 += r1.y;
            }
            *(float2*)(C + (size_t)row * 512 + col)       = make_float2(v0, v1);
            *(float2*)(C + (size_t)(row + 8) * 512 + col) = make_float2(v2, v3);
        }
    }
}

__global__ __launch_bounds__(256) void gemm_mma_b16(
    const float* __restrict__ A, const float* __restrict__ W,
    const float* __restrict__ bias, __nv_bfloat16* __restrict__ C, float scale)
{
    __shared__ uint32_t As[64][36];
    __shared__ uint32_t Ws[128][36];
    const int tid = threadIdx.x, wid = tid >> 5, lane = tid & 31;
    GemmCtx cx;
    cx.g = lane >> 2; cx.t = lane & 3;
    cx.wm = wid >> 2; cx.wn = wid & 3;
    cx.m0 = blockIdx.y * 64; cx.n0 = blockIdx.x * 128;
    float acc[2][4][4];
    gemm_mainloop(A, W, As, Ws, cx, acc);

#pragma unroll
    for (int im = 0; im < 2; im++) {
#pragma unroll
        for (int jn = 0; jn < 4; jn++) {
            const int row = cx.m0 + cx.wm * 32 + im * 16 + cx.g;
            const int col = cx.n0 + cx.wn * 32 + jn * 8 + 2 * cx.t;
            const float b0 = bias[col], b1 = bias[col + 1];
            const float v0 = (acc[im][jn][0] + b0) * scale;
            const float v1 = (acc[im][jn][1] + b1) * scale;
            const float v2 = (acc[im][jn][2] + b0) * scale;
            const float v3 = (acc[im][jn][3] + b1) * scale;
            *(uint32_t*)(C + (size_t)row * 512 + col)       = pk(v0, v1);
            *(uint32_t*)(C + (size_t)(row + 8) * 512 + col) = pk(v2, v3);
        }
    }
}

// ============================================================================
// bf16 flash attention. Per (b,h): 128 q-rows/block, 64 keys/iter, 8 warps.
// Warp owns 16 q-rows (warp-local online softmax, base-2 exp).
// Q/K/V bf16 from global (Q pre-scaled by QSCALE in projection GEMM).
// K/V streamed via cp.async into a 4-slot ring -> one __syncthreads/iter.
// P stays in registers (C-fragment == next A-fragment, packed bf16x2).
// SMEM: Qs 128x(64+8)bf16 =18432; K/V: 4 slots x 64x(64+8)bf16 =9216 each.
// ============================================================================
#define ROWB 144                     // (64+8) bf16 = 144 bytes per tile row
#define KVSZ 9216                    // 64 * 144
#define AT_SMEM (18432 + 8*KVSZ)     // 92160
__global__ __launch_bounds__(256, 2) void attn_mma()
{
    extern __shared__ __align__(16) char sm[];
    const uint32_t sb = smem_u32(sm);
    const uint32_t smQ = sb;
    const uint32_t smK0 = sb + 18432, smV0 = sb + 18432 + 4 * KVSZ;

    const int tid = threadIdx.x, wid = tid >> 5, lane = tid & 31;
    const int g = lane >> 2, t = lane & 3;
    const int sel = lane >> 3, r8 = lane & 7;
    const int sello = sel & 1, selhi = sel >> 1;

    const int bh = blockIdx.y;
    const size_t base = (size_t)(bh >> 3) * SS * DD + (size_t)(bh & 7) * 64;
    const __nv_bfloat16* qp = g_q + base;
    const __nv_bfloat16* kp = g_k + base;
    const __nv_bfloat16* vp = g_v + base;
    float* op = g_ctx + base;
    const int q0 = blockIdx.x * 128;
    const int qr = wid * 16;

    // ---- issue K/V tiles 0 and 1; stage Q ----
#pragma unroll
    for (int kb = 0; kb < 2; kb++) {
        const uint32_t dK = smK0 + kb * KVSZ, dV = smV0 + kb * KVSZ;
#pragma unroll
        for (int o = 0; o < 2; o++) {
            const int lin = tid + 256 * o, row = lin >> 3, seg = lin & 7;
            cpa(dK + row * ROWB + seg * 16, kp + (size_t)(kb * 64 + row) * 512 + seg * 8);
            cpa(dV + row * ROWB + seg * 16, vp + (size_t)(kb * 64 + row) * 512 + seg * 8);
        }
        CP_COMMIT();
    }
#pragma unroll
    for (int it = 0; it < 4; it++) {
        const int lin = tid + 256 * it, row = lin >> 3, seg = lin & 7;
        uint4 u = *(const uint4*)(qp + (size_t)(q0 + row) * 512 + seg * 8);
        *(uint4*)(sm + row * ROWB + seg * 16) = u;
    }
    __syncthreads();

    // Q fragments (a-layout): qf[ks] covers d = 16ks..16ks+15
    uint32_t qf[4][4];
#pragma unroll
    for (int ks = 0; ks < 4; ks++) {
        const uint32_t addr = smQ + (uint32_t)((qr + r8 + sello * 8) * ROWB + (16 * ks + selhi * 8) * 2);
        ldsm4(qf[ks], addr);
    }

    float oacc[8][4];
#pragma unroll
    for (int j = 0; j < 8; j++)
#pragma unroll
        for (int e = 0; e < 4; e++) oacc[j][e] = 0.f;
    float m0r = -1e30f, m1r = -1e30f, l0 = 0.f, l1 = 0.f;

    for (int kb = 0; kb < SS / 64; kb++) {
        // issue tile kb+2 into ring slot (kb+2)&3
        if (kb + 2 < SS / 64) {
            const int nb = kb + 2;
            const uint32_t dK = smK0 + (nb & 3) * KVSZ, dV = smV0 + (nb & 3) * KVSZ;
#pragma unroll
            for (int o = 0; o < 2; o++) {
                const int lin = tid + 256 * o, row = lin >> 3, seg = lin & 7;
                cpa(dK + row * ROWB + seg * 16, kp + (size_t)(nb * 64 + row) * 512 + seg * 8);
                cpa(dV + row * ROWB + seg * 16, vp + (size_t)(nb * 64 + row) * 512 + seg * 8);
            }
            CP_COMMIT();
            CP_WAIT(2);
        } else if (kb + 1 < SS / 64) {
            CP_WAIT(1);
        } else {
            CP_WAIT(0);
        }
        __syncthreads();

        const uint32_t smK = smK0 + (kb & 3) * KVSZ;
        const uint32_t smV = smV0 + (kb & 3) * KVSZ;

        // ---- S = Q . K^T (16 x 64 per warp), scores already in log2 units ----
        float sacc[8][4];
#pragma unroll
        for (int j = 0; j < 8; j++)
#pragma unroll
            for (int e = 0; e < 4; e++) sacc[j][e] = 0.f;
#pragma unroll
        for (int ks = 0; ks < 4; ks++) {
#pragma unroll
            for (int jp = 0; jp < 4; jp++) {
                uint32_t kf[4];
                const uint32_t addr = smK + (uint32_t)((jp * 16 + r8 + selhi * 8) * ROWB
                                                       + (16 * ks + sello * 8) * 2);
                ldsm4(kf, addr);
                mma16(sacc[2 * jp],     qf[ks], kf);
                mma16(sacc[2 * jp + 1], qf[ks], kf + 2);
            }
        }

        // ---- warp-local online softmax (base 2); rows qr+g, qr+8+g ----
        float mx0 = -1e30f, mx1 = -1e30f;
#pragma unroll
        for (int jn = 0; jn < 8; jn++) {
            mx0 = fmaxf(mx0, fmaxf(sacc[jn][0], sacc[jn][1]));
            mx1 = fmaxf(mx1, fmaxf(sacc[jn][2], sacc[jn][3]));
        }
        mx0 = fmaxf(mx0, __shfl_xor_sync(0xffffffffu, mx0, 1));
        mx0 = fmaxf(mx0, __shfl_xor_sync(0xffffffffu, mx0, 2));
        mx1 = fmaxf(mx1, __shfl_xor_sync(0xffffffffu, mx1, 1));
        mx1 = fmaxf(mx1, __shfl_xor_sync(0xffffffffu, mx1, 2));
        const float mn0 = fmaxf(m0r, mx0), mn1 = fmaxf(m1r, mx1);
        const float c0 = ex2(m0r - mn0), c1 = ex2(m1r - mn1);

        float s0 = 0.f, s1 = 0.f;
#pragma unroll
        for (int jn = 0; jn < 8; jn++) {
            sacc[jn][0] = ex2(sacc[jn][0] - mn0);
            sacc[jn][1] = ex2(sacc[jn][1] - mn0);
            sacc[jn][2] = ex2(sacc[jn][2] - mn1);
            sacc[jn][3] = ex2(sacc[jn][3] - mn1);
            s0 += sacc[jn][0] + sacc[jn][1];
            s1 += sacc[jn][2] + sacc[jn][3];
        }
        s0 += __shfl_xor_sync(0xffffffffu, s0, 1);
        s0 += __shfl_xor_sync(0xffffffffu, s0, 2);
        s1 += __shfl_xor_sync(0xffffffffu, s1, 1);
        s1 += __shfl_xor_sync(0xffffffffu, s1, 2);
        l0 = l0 * c0 + s0; l1 = l1 * c1 + s1;
        m0r = mn0; m1r = mn1;
#pragma unroll
        for (int jd = 0; jd < 8; jd++) {
            oacc[jd][0] *= c0; oacc[jd][1] *= c0;
            oacc[jd][2] *= c1; oacc[jd][3] *= c1;
        }

        // ---- P -> bf16x2 a-fragments (registers only) ----
        uint32_t pf[4][4];
#pragma unroll
        for (int ks = 0; ks < 4; ks++) {
            pf[ks][0] = pk(sacc[2 * ks][0],     sacc[2 * ks][1]);
            pf[ks][1] = pk(sacc[2 * ks][2],     sacc[2 * ks][3]);
            pf[ks][2] = pk(sacc[2 * ks + 1][0], sacc[2 * ks + 1][1]);
            pf[ks][3] = pk(sacc[2 * ks + 1][2], sacc[2 * ks + 1][3]);
        }

        // ---- O += P . V (V fragments via ldmatrix.trans) ----
#pragma unroll
        for (int ks = 0; ks < 4; ks++) {
#pragma unroll
            for (int jp = 0; jp < 4; jp++) {
                uint32_t vf[4];
                const uint32_t addr = smV + (uint32_t)((16 * ks + r8 + sello * 8) * ROWB
                                                       + (2 * jp + selhi) * 16);
                ldsm4t(vf, addr);
                mma16(oacc[2 * jp],     pf[ks], vf);
                mma16(oacc[2 * jp + 1], pf[ks], vf + 2);
            }
        }
    }

    const float inv0 = 1.f / l0, inv1 = 1.f / l1;
#pragma unroll
    for (int jd = 0; jd < 8; jd++) {
        const int col = jd * 8 + 2 * t;
        *(float2*)(op + (size_t)(q0 + qr + g) * 512 + col) =
            make_float2(oacc[jd][0] * inv0, oacc[jd][1] * inv0);
        *(float2*)(op + (size_t)(q0 + qr + 8 + g) * 512 + col) =
            make_float2(oacc[jd][2] * inv1, oacc[jd][3] * inv1);
    }
}

// ============================================================================
// LayerNorm: one block (128 thr) per token row of 512
// ============================================================================
__global__ __launch_bounds__(128) void ln_kernel(
    const float* __restrict__ y, const float* __restrict__ gamma,
    const float* __restrict__ beta, float* __restrict__ out)
{
    const int row = blockIdx.x;
    const float* yr = y + (size_t)row * DD;
    float v[4], s = 0.f, s2 = 0.f;
#pragma unroll
    for (int i = 0; i < 4; i++) {
        float x = yr[threadIdx.x + i * 128];
        v[i] = x; s += x; s2 += x * x;
    }
#pragma unroll
    for (int o = 16; o; o >>= 1) {
        s  += __shfl_xor_sync(0xffffffffu, s, o);
        s2 += __shfl_xor_sync(0xffffffffu, s2, o);
    }
    __shared__ float sh[8];
    const int w = threadIdx.x >> 5;
    if ((threadIdx.x & 31) == 0) { sh[w] = s; sh[w + 4] = s2; }
    __syncthreads();
    s  = sh[0] + sh[1] + sh[2] + sh[3];
    s2 = sh[4] + sh[5] + sh[6] + sh[7];
    const float mu   = s * (1.f / DD);
    const float var  = s2 * (1.f / DD) - mu * mu;
    const float rstd = rsqrtf(var + 1e-5f);
    float* orow = out + (size_t)row * DD;
#pragma unroll
    for (int i = 0; i < 4; i++) {
        const int c = threadIdx.x + i * 128;
        orow[c] = (v[i] - mu) * rstd * gamma[c] + beta[c];
    }
}

// ============================================================================
extern "C" void kernel_launch(void* const* d_in, const int* in_sizes, int n_in,
                              void* d_out, int out_size)
{
    const float* x     = (const float*)d_in[0];
    const float* Wq    = (const float*)d_in[1];
    const float* bq    = (const float*)d_in[2];
    const float* Wk    = (const float*)d_in[3];
    const float* bk    = (const float*)d_in[4];
    const float* Wv    = (const float*)d_in[5];
    const float* bv    = (const float*)d_in[6];
    const float* Wo    = (const float*)d_in[7];
    const float* bo    = (const float*)d_in[8];
    const float* gamma = (const float*)d_in[9];
    const float* beta  = (const float*)d_in[10];
    float* out = (float*)d_out;

    __nv_bfloat16 *qp, *kp, *vp;
    float *cp, *yp;
    cudaGetSymbolAddress((void**)&qp, g_q);
    cudaGetSymbolAddress((void**)&kp, g_k);
    cudaGetSymbolAddress((void**)&vp, g_v);
    cudaGetSymbolAddress((void**)&cp, g_ctx);
    cudaGetSymbolAddress((void**)&yp, g_y);

    cudaFuncSetAttribute(attn_mma, cudaFuncAttributeMaxDynamicSharedMemorySize, AT_SMEM);

    dim3 gg(4, 128);   // N/128, M/64
    gemm_mma_b16<<<gg, 256>>>(x, Wq, bq, qp, QSCALE);
    gemm_mma_b16<<<gg, 256>>>(x, Wk, bk, kp, 1.f);
    gemm_mma_b16<<<gg, 256>>>(x, Wv, bv, vp, 1.f);

    attn_mma<<<dim3(SS / 128, BB * HH), 256, AT_SMEM>>>();

    gemm_mma<<<gg, 256>>>(cp, Wo, bo, x, yp);

    ln_kernel<<<MTOK, 128>>>(yp, gamma, beta, out);
}

// round 7
// speedup vs baseline: 6.0472x; 1.3663x over previous
#include <cuda_runtime.h>
#include <cuda_bf16.h>
#include <cstdint>

#define BB 4
#define SS 2048
#define DD 512
#define HH 8
#define MTOK (BB*SS)
#define QSCALE (0.125f * 1.44269504f)   // 1/sqrt(dk) * log2(e)

// Scratch (module-load allocated; no cudaMalloc anywhere)
__device__ __align__(256) __nv_bfloat16 g_x16[MTOK*DD];
__device__ __align__(256) __nv_bfloat16 g_wq[DD*DD];
__device__ __align__(256) __nv_bfloat16 g_wk[DD*DD];
__device__ __align__(256) __nv_bfloat16 g_wv[DD*DD];
__device__ __align__(256) __nv_bfloat16 g_wo[DD*DD];
__device__ __align__(256) __nv_bfloat16 g_q[MTOK*DD];
__device__ __align__(256) __nv_bfloat16 g_k[MTOK*DD];
__device__ __align__(256) __nv_bfloat16 g_v[MTOK*DD];
__device__ __align__(256) __nv_bfloat16 g_ctx[MTOK*DD];
__device__ float g_y[MTOK*DD];

// ======================= helpers ===========================================
__device__ __forceinline__ uint32_t pk(float lo, float hi) {
    uint32_t r; asm("cvt.rn.bf16x2.f32 %0, %1, %2;" : "=r"(r) : "f"(hi), "f"(lo)); return r;
}
__device__ __forceinline__ float ex2(float x) {
    float r; asm("ex2.approx.f32 %0, %1;" : "=f"(r) : "f"(x)); return r;
}
__device__ __forceinline__ uint32_t smem_u32(const void* p) {
    uint32_t a;
    asm("{ .reg .u64 t; cvta.to.shared.u64 t, %1; cvt.u32.u64 %0, t; }" : "=r"(a) : "l"(p));
    return a;
}
__device__ __forceinline__ void mma16(float* d, const uint32_t* a, const uint32_t* b) {
    asm volatile(
        "mma.sync.aligned.m16n8k16.row.col.f32.bf16.bf16.f32 "
        "{%0,%1,%2,%3}, {%4,%5,%6,%7}, {%8,%9}, {%0,%1,%2,%3};"
        : "+f"(d[0]), "+f"(d[1]), "+f"(d[2]), "+f"(d[3])
        : "r"(a[0]), "r"(a[1]), "r"(a[2]), "r"(a[3]), "r"(b[0]), "r"(b[1]));
}
__device__ __forceinline__ void ldsm4(uint32_t* r, uint32_t addr) {
    asm volatile("ldmatrix.sync.aligned.m8n8.x4.shared.b16 {%0,%1,%2,%3}, [%4];"
        : "=r"(r[0]), "=r"(r[1]), "=r"(r[2]), "=r"(r[3]) : "r"(addr));
}
__device__ __forceinline__ void ldsm4t(uint32_t* r, uint32_t addr) {
    asm volatile("ldmatrix.sync.aligned.m8n8.x4.trans.shared.b16 {%0,%1,%2,%3}, [%4];"
        : "=r"(r[0]), "=r"(r[1]), "=r"(r[2]), "=r"(r[3]) : "r"(addr));
}
__device__ __forceinline__ void cpa(uint32_t dst, const void* src) {
    asm volatile("cp.async.ca.shared.global [%0], [%1], 16;" :: "r"(dst), "l"(src) : "memory");
}
#define CP_COMMIT() asm volatile("cp.async.commit_group;" ::: "memory")
#define CP_WAIT(n)  asm volatile("cp.async.wait_group %0;" :: "n"(n) : "memory")

// ============================================================================
// fp32 -> bf16 conversion (x and weights), 4 elems/thread
// ============================================================================
__global__ __launch_bounds__(256) void cvt_kernel(
    const float* __restrict__ in, __nv_bfloat16* __restrict__ out, int n4)
{
    const int i = blockIdx.x * blockDim.x + threadIdx.x;
    if (i < n4) {
        float4 v = ((const float4*)in)[i];
        uint2 u = { pk(v.x, v.y), pk(v.z, v.w) };
        *(uint2*)(out + (size_t)i * 4) = u;
    }
}

// ============================================================================
// bf16 GEMM mainloop: C[m][n] = sum_k A[m][k]*W[n][k]; tile 128x128, BK=64,
// 8 warps 2(m)x4(n), warp tile 64x32. cp.async 3-stage ring, ldmatrix frags.
// acc[4][4][4]: 4 mtiles(16) x 4 ntiles(8).
// ============================================================================
#define GROWB 144                    // 64 bf16 + 8 pad = 144 bytes
#define GTILE (128*GROWB)            // 18432 per operand per stage
#define G_SMEM (3*2*GTILE)           // 110592

struct GCtx { int m0, n0, wm, wn, g, t, r8, sello, selhi; };

__device__ __forceinline__ void gemm16_mainloop(
    const __nv_bfloat16* __restrict__ A, const __nv_bfloat16* __restrict__ W,
    uint32_t sb, const GCtx& cx, float acc[4][4][4])
{
    const int tid = threadIdx.x;
#pragma unroll
    for (int mt = 0; mt < 4; mt++)
#pragma unroll
        for (int jn = 0; jn < 4; jn++)
#pragma unroll
            for (int e = 0; e < 4; e++) acc[mt][jn][e] = 0.f;

    const int ldrow = tid >> 1;          // 0..127
    const int ldseg = (tid & 1) * 4;     // 0 or 4 (each thread: 4 consecutive 16B segs)

    // prologue: chunks 0,1 into stages 0,1
#pragma unroll
    for (int ch = 0; ch < 2; ch++) {
        const uint32_t sA = sb + ch * 2 * GTILE, sW = sA + GTILE;
#pragma unroll
        for (int s = 0; s < 4; s++) {
            cpa(sA + ldrow * GROWB + (ldseg + s) * 16,
                A + (size_t)(cx.m0 + ldrow) * 512 + ch * 64 + (ldseg + s) * 8);
            cpa(sW + ldrow * GROWB + (ldseg + s) * 16,
                W + (size_t)(cx.n0 + ldrow) * 512 + ch * 64 + (ldseg + s) * 8);
        }
        CP_COMMIT();
    }

    for (int ch = 0; ch < 8; ch++) {
        if (ch + 2 < 8) {
            const int nc = ch + 2, st = nc % 3;
            const uint32_t sA = sb + st * 2 * GTILE, sW = sA + GTILE;
#pragma unroll
            for (int s = 0; s < 4; s++) {
                cpa(sA + ldrow * GROWB + (ldseg + s) * 16,
                    A + (size_t)(cx.m0 + ldrow) * 512 + nc * 64 + (ldseg + s) * 8);
                cpa(sW + ldrow * GROWB + (ldseg + s) * 16,
                    W + (size_t)(cx.n0 + ldrow) * 512 + nc * 64 + (ldseg + s) * 8);
            }
            CP_COMMIT();
            CP_WAIT(2);
        } else if (ch + 1 < 8) {
            CP_WAIT(1);
        } else {
            CP_WAIT(0);
        }
        __syncthreads();

        const uint32_t sA = sb + (ch % 3) * 2 * GTILE, sW = sA + GTILE;
#pragma unroll
        for (int ks = 0; ks < 4; ks++) {
            uint32_t af[4][4];
#pragma unroll
            for (int mt = 0; mt < 4; mt++)
                ldsm4(af[mt], sA + (uint32_t)((cx.wm * 64 + mt * 16 + cx.r8 + cx.sello * 8) * GROWB
                                              + (ks * 16 + cx.selhi * 8) * 2));
#pragma unroll
            for (int p = 0; p < 2; p++) {
                uint32_t wf[4];
                ldsm4(wf, sW + (uint32_t)((cx.wn * 32 + p * 16 + cx.r8 + cx.selhi * 8) * GROWB
                                          + (ks * 16 + cx.sello * 8) * 2));
#pragma unroll
                for (int mt = 0; mt < 4; mt++) {
                    mma16(acc[mt][2 * p],     af[mt], wf);
                    mma16(acc[mt][2 * p + 1], af[mt], wf + 2);
                }
            }
        }
        __syncthreads();
    }
}

// QKV flavor: bf16 output, (acc + bias) * scale
__global__ __launch_bounds__(256, 2) void gemm16_b16(
    const __nv_bfloat16* __restrict__ A, const __nv_bfloat16* __restrict__ W,
    const float* __restrict__ bias, __nv_bfloat16* __restrict__ C, float scale)
{
    extern __shared__ __align__(16) char smg[];
    const uint32_t sb = smem_u32(smg);
    const int tid = threadIdx.x, wid = tid >> 5, lane = tid & 31;
    GCtx cx;
    cx.g = lane >> 2; cx.t = lane & 3;
    cx.r8 = lane & 7; cx.sello = (lane >> 3) & 1; cx.selhi = lane >> 4;
    cx.wm = wid >> 2; cx.wn = wid & 3;
    cx.m0 = blockIdx.y * 128; cx.n0 = blockIdx.x * 128;
    float acc[4][4][4];
    gemm16_mainloop(A, W, sb, cx, acc);

#pragma unroll
    for (int mt = 0; mt < 4; mt++) {
#pragma unroll
        for (int jn = 0; jn < 4; jn++) {
            const int row = cx.m0 + cx.wm * 64 + mt * 16 + cx.g;
            const int col = cx.n0 + cx.wn * 32 + jn * 8 + 2 * cx.t;
            const float b0 = bias[col], b1 = bias[col + 1];
            *(uint32_t*)(C + (size_t)row * 512 + col) =
                pk((acc[mt][jn][0] + b0) * scale, (acc[mt][jn][1] + b1) * scale);
            *(uint32_t*)(C + (size_t)(row + 8) * 512 + col) =
                pk((acc[mt][jn][2] + b0) * scale, (acc[mt][jn][3] + b1) * scale);
        }
    }
}

// O-proj flavor: fp32 output, acc + bias + residual
__global__ __launch_bounds__(256, 2) void gemm16_f32(
    const __nv_bfloat16* __restrict__ A, const __nv_bfloat16* __restrict__ W,
    const float* __restrict__ bias, const float* __restrict__ res,
    float* __restrict__ C)
{
    extern __shared__ __align__(16) char smg[];
    const uint32_t sb = smem_u32(smg);
    const int tid = threadIdx.x, wid = tid >> 5, lane = tid & 31;
    GCtx cx;
    cx.g = lane >> 2; cx.t = lane & 3;
    cx.r8 = lane & 7; cx.sello = (lane >> 3) & 1; cx.selhi = lane >> 4;
    cx.wm = wid >> 2; cx.wn = wid & 3;
    cx.m0 = blockIdx.y * 128; cx.n0 = blockIdx.x * 128;
    float acc[4][4][4];
    gemm16_mainloop(A, W, sb, cx, acc);

#pragma unroll
    for (int mt = 0; mt < 4; mt++) {
#pragma unroll
        for (int jn = 0; jn < 4; jn++) {
            const int row = cx.m0 + cx.wm * 64 + mt * 16 + cx.g;
            const int col = cx.n0 + cx.wn * 32 + jn * 8 + 2 * cx.t;
            const float b0 = bias[col], b1 = bias[col + 1];
            float2 r0 = *(const float2*)(res + (size_t)row * 512 + col);
            float2 r1 = *(const float2*)(res + (size_t)(row + 8) * 512 + col);
            *(float2*)(C + (size_t)row * 512 + col) =
                make_float2(acc[mt][jn][0] + b0 + r0.x, acc[mt][jn][1] + b1 + r0.y);
            *(float2*)(C + (size_t)(row + 8) * 512 + col) =
                make_float2(acc[mt][jn][2] + b0 + r1.x, acc[mt][jn][3] + b1 + r1.y);
        }
    }
}

// ============================================================================
// bf16 flash attention (as round 6), ctx now written as bf16.
// ============================================================================
#define ROWB 144
#define KVSZ 9216
#define AT_SMEM (18432 + 8*KVSZ)     // 92160
__global__ __launch_bounds__(256, 2) void attn_mma()
{
    extern __shared__ __align__(16) char sm[];
    const uint32_t sb = smem_u32(sm);
    const uint32_t smQ = sb;
    const uint32_t smK0 = sb + 18432, smV0 = sb + 18432 + 4 * KVSZ;

    const int tid = threadIdx.x, wid = tid >> 5, lane = tid & 31;
    const int g = lane >> 2, t = lane & 3;
    const int sel = lane >> 3, r8 = lane & 7;
    const int sello = sel & 1, selhi = sel >> 1;

    const int bh = blockIdx.y;
    const size_t base = (size_t)(bh >> 3) * SS * DD + (size_t)(bh & 7) * 64;
    const __nv_bfloat16* qp = g_q + base;
    const __nv_bfloat16* kp = g_k + base;
    const __nv_bfloat16* vp = g_v + base;
    __nv_bfloat16* op = g_ctx + base;
    const int q0 = blockIdx.x * 128;
    const int qr = wid * 16;

#pragma unroll
    for (int kb = 0; kb < 2; kb++) {
        const uint32_t dK = smK0 + kb * KVSZ, dV = smV0 + kb * KVSZ;
#pragma unroll
        for (int o = 0; o < 2; o++) {
            const int lin = tid + 256 * o, row = lin >> 3, seg = lin & 7;
            cpa(dK + row * ROWB + seg * 16, kp + (size_t)(kb * 64 + row) * 512 + seg * 8);
            cpa(dV + row * ROWB + seg * 16, vp + (size_t)(kb * 64 + row) * 512 + seg * 8);
        }
        CP_COMMIT();
    }
#pragma unroll
    for (int it = 0; it < 4; it++) {
        const int lin = tid + 256 * it, row = lin >> 3, seg = lin & 7;
        uint4 u = *(const uint4*)(qp + (size_t)(q0 + row) * 512 + seg * 8);
        *(uint4*)(sm + row * ROWB + seg * 16) = u;
    }
    __syncthreads();

    uint32_t qf[4][4];
#pragma unroll
    for (int ks = 0; ks < 4; ks++) {
        const uint32_t addr = smQ + (uint32_t)((qr + r8 + sello * 8) * ROWB + (16 * ks + selhi * 8) * 2);
        ldsm4(qf[ks], addr);
    }

    float oacc[8][4];
#pragma unroll
    for (int j = 0; j < 8; j++)
#pragma unroll
        for (int e = 0; e < 4; e++) oacc[j][e] = 0.f;
    float m0r = -1e30f, m1r = -1e30f, l0 = 0.f, l1 = 0.f;

    for (int kb = 0; kb < SS / 64; kb++) {
        if (kb + 2 < SS / 64) {
            const int nb = kb + 2;
            const uint32_t dK = smK0 + (nb & 3) * KVSZ, dV = smV0 + (nb & 3) * KVSZ;
#pragma unroll
            for (int o = 0; o < 2; o++) {
                const int lin = tid + 256 * o, row = lin >> 3, seg = lin & 7;
                cpa(dK + row * ROWB + seg * 16, kp + (size_t)(nb * 64 + row) * 512 + seg * 8);
                cpa(dV + row * ROWB + seg * 16, vp + (size_t)(nb * 64 + row) * 512 + seg * 8);
            }
            CP_COMMIT();
            CP_WAIT(2);
        } else if (kb + 1 < SS / 64) {
            CP_WAIT(1);
        } else {
            CP_WAIT(0);
        }
        __syncthreads();

        const uint32_t smK = smK0 + (kb & 3) * KVSZ;
        const uint32_t smV = smV0 + (kb & 3) * KVSZ;

        float sacc[8][4];
#pragma unroll
        for (int j = 0; j < 8; j++)
#pragma unroll
            for (int e = 0; e < 4; e++) sacc[j][e] = 0.f;
#pragma unroll
        for (int ks = 0; ks < 4; ks++) {
#pragma unroll
            for (int jp = 0; jp < 4; jp++) {
                uint32_t kf[4];
                const uint32_t addr = smK + (uint32_t)((jp * 16 + r8 + selhi * 8) * ROWB
                                                       + (16 * ks + sello * 8) * 2);
                ldsm4(kf, addr);
                mma16(sacc[2 * jp],     qf[ks], kf);
                mma16(sacc[2 * jp + 1], qf[ks], kf + 2);
            }
        }

        float mx0 = -1e30f, mx1 = -1e30f;
#pragma unroll
        for (int jn = 0; jn < 8; jn++) {
            mx0 = fmaxf(mx0, fmaxf(sacc[jn][0], sacc[jn][1]));
            mx1 = fmaxf(mx1, fmaxf(sacc[jn][2], sacc[jn][3]));
        }
        mx0 = fmaxf(mx0, __shfl_xor_sync(0xffffffffu, mx0, 1));
        mx0 = fmaxf(mx0, __shfl_xor_sync(0xffffffffu, mx0, 2));
        mx1 = fmaxf(mx1, __shfl_xor_sync(0xffffffffu, mx1, 1));
        mx1 = fmaxf(mx1, __shfl_xor_sync(0xffffffffu, mx1, 2));
        const float mn0 = fmaxf(m0r, mx0), mn1 = fmaxf(m1r, mx1);
        const float c0 = ex2(m0r - mn0), c1 = ex2(m1r - mn1);

        float s0 = 0.f, s1 = 0.f;
#pragma unroll
        for (int jn = 0; jn < 8; jn++) {
            sacc[jn][0] = ex2(sacc[jn][0] - mn0);
            sacc[jn][1] = ex2(sacc[jn][1] - mn0);
            sacc[jn][2] = ex2(sacc[jn][2] - mn1);
            sacc[jn][3] = ex2(sacc[jn][3] - mn1);
            s0 += sacc[jn][0] + sacc[jn][1];
            s1 += sacc[jn][2] + sacc[jn][3];
        }
        s0 += __shfl_xor_sync(0xffffffffu, s0, 1);
        s0 += __shfl_xor_sync(0xffffffffu, s0, 2);
        s1 += __shfl_xor_sync(0xffffffffu, s1, 1);
        s1 += __shfl_xor_sync(0xffffffffu, s1, 2);
        l0 = l0 * c0 + s0; l1 = l1 * c1 + s1;
        m0r = mn0; m1r = mn1;
#pragma unroll
        for (int jd = 0; jd < 8; jd++) {
            oacc[jd][0] *= c0; oacc[jd][1] *= c0;
            oacc[jd][2] *= c1; oacc[jd][3] *= c1;
        }

        uint32_t pf[4][4];
#pragma unroll
        for (int ks = 0; ks < 4; ks++) {
            pf[ks][0] = pk(sacc[2 * ks][0],     sacc[2 * ks][1]);
            pf[ks][1] = pk(sacc[2 * ks][2],     sacc[2 * ks][3]);
            pf[ks][2] = pk(sacc[2 * ks + 1][0], sacc[2 * ks + 1][1]);
            pf[ks][3] = pk(sacc[2 * ks + 1][2], sacc[2 * ks + 1][3]);
        }

#pragma unroll
        for (int ks = 0; ks < 4; ks++) {
#pragma unroll
            for (int jp = 0; jp < 4; jp++) {
                uint32_t vf[4];
                const uint32_t addr = smV + (uint32_t)((16 * ks + r8 + sello * 8) * ROWB
                                                       + (2 * jp + selhi) * 16);
                ldsm4t(vf, addr);
                mma16(oacc[2 * jp],     pf[ks], vf);
                mma16(oacc[2 * jp + 1], pf[ks], vf + 2);
            }
        }
    }

    const float inv0 = 1.f / l0, inv1 = 1.f / l1;
#pragma unroll
    for (int jd = 0; jd < 8; jd++) {
        const int col = jd * 8 + 2 * t;
        *(uint32_t*)(op + (size_t)(q0 + qr + g) * 512 + col) =
            pk(oacc[jd][0] * inv0, oacc[jd][1] * inv0);
        *(uint32_t*)(op + (size_t)(q0 + qr + 8 + g) * 512 + col) =
            pk(oacc[jd][2] * inv1, oacc[jd][3] * inv1);
    }
}

// ============================================================================
// LayerNorm: one block (128 thr) per token row of 512
// ============================================================================
__global__ __launch_bounds__(128) void ln_kernel(
    const float* __restrict__ y, const float* __restrict__ gamma,
    const float* __restrict__ beta, float* __restrict__ out)
{
    const int row = blockIdx.x;
    const float* yr = y + (size_t)row * DD;
    float v[4], s = 0.f, s2 = 0.f;
#pragma unroll
    for (int i = 0; i < 4; i++) {
        float x = yr[threadIdx.x + i * 128];
        v[i] = x; s += x; s2 += x * x;
    }
#pragma unroll
    for (int o = 16; o; o >>= 1) {
        s  += __shfl_xor_sync(0xffffffffu, s, o);
        s2 += __shfl_xor_sync(0xffffffffu, s2, o);
    }
    __shared__ float sh[8];
    const int w = threadIdx.x >> 5;
    if ((threadIdx.x & 31) == 0) { sh[w] = s; sh[w + 4] = s2; }
    __syncthreads();
    s  = sh[0] + sh[1] + sh[2] + sh[3];
    s2 = sh[4] + sh[5] + sh[6] + sh[7];
    const float mu   = s * (1.f / DD);
    const float var  = s2 * (1.f / DD) - mu * mu;
    const float rstd = rsqrtf(var + 1e-5f);
    float* orow = out + (size_t)row * DD;
#pragma unroll
    for (int i = 0; i < 4; i++) {
        const int c = threadIdx.x + i * 128;
        orow[c] = (v[i] - mu) * rstd * gamma[c] + beta[c];
    }
}

// ============================================================================
extern "C" void kernel_launch(void* const* d_in, const int* in_sizes, int n_in,
                              void* d_out, int out_size)
{
    const float* x     = (const float*)d_in[0];
    const float* Wq    = (const float*)d_in[1];
    const float* bq    = (const float*)d_in[2];
    const float* Wk    = (const float*)d_in[3];
    const float* bk    = (const float*)d_in[4];
    const float* Wv    = (const float*)d_in[5];
    const float* bv    = (const float*)d_in[6];
    const float* Wo    = (const float*)d_in[7];
    const float* bo    = (const float*)d_in[8];
    const float* gamma = (const float*)d_in[9];
    const float* beta  = (const float*)d_in[10];
    float* out = (float*)d_out;

    __nv_bfloat16 *x16, *wq, *wk, *wv, *wo, *qp, *kp, *vp, *cp;
    float *yp;
    cudaGetSymbolAddress((void**)&x16, g_x16);
    cudaGetSymbolAddress((void**)&wq, g_wq);
    cudaGetSymbolAddress((void**)&wk, g_wk);
    cudaGetSymbolAddress((void**)&wv, g_wv);
    cudaGetSymbolAddress((void**)&wo, g_wo);
    cudaGetSymbolAddress((void**)&qp, g_q);
    cudaGetSymbolAddress((void**)&kp, g_k);
    cudaGetSymbolAddress((void**)&vp, g_v);
    cudaGetSymbolAddress((void**)&cp, g_ctx);
    cudaGetSymbolAddress((void**)&yp, g_y);

    cudaFuncSetAttribute(attn_mma, cudaFuncAttributeMaxDynamicSharedMemorySize, AT_SMEM);
    cudaFuncSetAttribute(gemm16_b16, cudaFuncAttributeMaxDynamicSharedMemorySize, G_SMEM);
    cudaFuncSetAttribute(gemm16_f32, cudaFuncAttributeMaxDynamicSharedMemorySize, G_SMEM);

    // convert x + weights to bf16
    cvt_kernel<<<(MTOK * DD / 4 + 255) / 256, 256>>>(x, x16, MTOK * DD / 4);
    cvt_kernel<<<(DD * DD / 4 + 255) / 256, 256>>>(Wq, wq, DD * DD / 4);
    cvt_kernel<<<(DD * DD / 4 + 255) / 256, 256>>>(Wk, wk, DD * DD / 4);
    cvt_kernel<<<(DD * DD / 4 + 255) / 256, 256>>>(Wv, wv, DD * DD / 4);
    cvt_kernel<<<(DD * DD / 4 + 255) / 256, 256>>>(Wo, wo, DD * DD / 4);

    dim3 gg(DD / 128, MTOK / 128);   // (4, 64)
    gemm16_b16<<<gg, 256, G_SMEM>>>(x16, wq, bq, qp, QSCALE);
    gemm16_b16<<<gg, 256, G_SMEM>>>(x16, wk, bk, kp, 1.f);
    gemm16_b16<<<gg, 256, G_SMEM>>>(x16, wv, bv, vp, 1.f);

    attn_mma<<<dim3(SS / 128, BB * HH), 256, AT_SMEM>>>();

    gemm16_f32<<<gg, 256, G_SMEM>>>(cp, wo, bo, x, yp);

    ln_kernel<<<MTOK, 128>>>(yp, gamma, beta, out);
}